// round 5
// baseline (speedup 1.0000x reference)
#include <cuda_runtime.h>
#include <cuda_bf16.h>

// CoralLossV2: mean over (B, Km1=64) of BCE-with-logits(logits, levels),
// levels[i,k] = (targets[i] > k).
//
// Identity: max(x,0) - x*z + log1p(exp(-|x|)) = softplus((1-2z)*x)
//         = ln2 * log2(1 + 2^(y*log2e)),  y = z ? -x : x
// -> 7 instrs/element (2 MUFU, ~4 fma, 1 sel), one accumulator.
//
// Grid 4096 fixed-work blocks (28v27 per SM = 2.6% tail vs 7.4% at 2048).
// Last block (atomic counter) does the deterministic final reduction.

#define NBLOCKS  4096
#define NTHREADS 256
#define NITER    8                       // vec4 per thread on the fast path
#define STRIDE   (NBLOCKS * NTHREADS)    // 1048576 = 2^20, multiple of 16
#define TSTEP    ((STRIDE >> 4) * 2)     // int32 stride into int64 targets

#define LOG2E 1.4426950408889634f
#define LN2   0.6931471805599453f

__device__ float g_partials[NBLOCKS];
__device__ unsigned int g_counter = 0;   // self-resetting each launch

__device__ __forceinline__ float ex2f(float x) {
    float r; asm("ex2.approx.ftz.f32 %0, %1;" : "=f"(r) : "f"(x)); return r;
}
__device__ __forceinline__ float lg2f(float x) {
    float r; asm("lg2.approx.ftz.f32 %0, %1;" : "=f"(r) : "f"(x)); return r;
}

// softplus((1-2z)x) in log2 units: log2(1 + 2^(y*log2e))
__device__ __forceinline__ void proc1(float x, bool z, float& acc2) {
    float y = z ? -x : x;
    float e = ex2f(y * LOG2E);
    acc2 += lg2f(1.0f + e);
}

__device__ __forceinline__ void proc4(float4 v, int c /* t - kbase */,
                                      float& acc2) {
    proc1(v.x, c > 0, acc2);
    proc1(v.y, c > 1, acc2);
    proc1(v.z, c > 2, acc2);
    proc1(v.w, c > 3, acc2);
}

__device__ __forceinline__ float block_reduce(float acc, float* warp_sums) {
    #pragma unroll
    for (int off = 16; off > 0; off >>= 1)
        acc += __shfl_xor_sync(0xFFFFFFFF, acc, off);
    int lane = threadIdx.x & 31;
    int wid  = threadIdx.x >> 5;
    if (lane == 0) warp_sums[wid] = acc;
    __syncthreads();
    float s = 0.0f;
    if (wid == 0) {
        s = (lane < NTHREADS / 32) ? warp_sums[lane] : 0.0f;
        #pragma unroll
        for (int off = 4; off > 0; off >>= 1)
            s += __shfl_xor_sync(0xFFFFFFFF, s, off);
    }
    return s;  // valid in warp 0 lane 0
}

__device__ __forceinline__ void finish(float bsum, float inv_n,
                                       float* __restrict__ out,
                                       float* warp_sums) {
    __shared__ bool is_last;
    if (threadIdx.x == 0) {
        g_partials[blockIdx.x] = bsum;
        __threadfence();
        unsigned int done = atomicAdd(&g_counter, 1u);
        is_last = (done == (unsigned int)(gridDim.x - 1));
    }
    __syncthreads();
    if (is_last) {
        float facc = 0.0f;
        for (int j = threadIdx.x; j < (int)gridDim.x; j += NTHREADS)
            facc += g_partials[j];
        __syncthreads();
        float fsum = block_reduce(facc, warp_sums);
        if (threadIdx.x == 0) {
            out[0] = fsum * inv_n;
            g_counter = 0;
        }
    }
}

__global__ __launch_bounds__(NTHREADS)
void coral_fast_kernel(const float4* __restrict__ logits4,
                       const int* __restrict__ targets32,
                       float inv_n, float* __restrict__ out) {
    const int tid = blockIdx.x * NTHREADS + threadIdx.x;
    const int kb  = (tid & 15) << 2;            // loop-invariant
    const float4* p  = logits4 + tid;
    const int*    tp = targets32 + ((tid >> 4) << 1);

    float acc2 = 0.0f;

    #pragma unroll
    for (int mm = 0; mm < NITER / 4; mm++) {
        float4 v0 = __ldcs(p + (size_t)(mm * 4 + 0) * STRIDE);
        float4 v1 = __ldcs(p + (size_t)(mm * 4 + 1) * STRIDE);
        float4 v2 = __ldcs(p + (size_t)(mm * 4 + 2) * STRIDE);
        float4 v3 = __ldcs(p + (size_t)(mm * 4 + 3) * STRIDE);
        int t0 = __ldg(tp + (mm * 4 + 0) * TSTEP);
        int t1 = __ldg(tp + (mm * 4 + 1) * TSTEP);
        int t2 = __ldg(tp + (mm * 4 + 2) * TSTEP);
        int t3 = __ldg(tp + (mm * 4 + 3) * TSTEP);
        proc4(v0, t0 - kb, acc2);
        proc4(v1, t1 - kb, acc2);
        proc4(v2, t2 - kb, acc2);
        proc4(v3, t3 - kb, acc2);
    }

    float acc = LN2 * acc2;

    __shared__ float warp_sums[NTHREADS / 32];
    float bsum = block_reduce(acc, warp_sums);
    finish(bsum, inv_n, out, warp_sums);
}

// Generic fallback (Km1 = 64 layout, arbitrary nvec)
__global__ __launch_bounds__(NTHREADS)
void coral_generic_kernel(const float4* __restrict__ logits4,
                          const int* __restrict__ targets32,
                          int nvec, float inv_n, float* __restrict__ out) {
    const int tid    = blockIdx.x * blockDim.x + threadIdx.x;
    const int stride = gridDim.x * blockDim.x;

    float acc2 = 0.0f;
    for (int i = tid; i < nvec; i += stride) {
        float4 v = logits4[i];
        int t = targets32[(i >> 4) * 2];
        proc4(v, t - ((i & 15) << 2), acc2);
    }
    float acc = LN2 * acc2;

    __shared__ float warp_sums[NTHREADS / 32];
    float bsum = block_reduce(acc, warp_sums);
    finish(bsum, inv_n, out, warp_sums);
}

extern "C" void kernel_launch(void* const* d_in, const int* in_sizes, int n_in,
                              void* d_out, int out_size) {
    const float4* logits4   = (const float4*)d_in[0];
    const int*    targets32 = (const int*)d_in[1];  // int64 low words (targets >= 0)
    float*        out       = (float*)d_out;

    long long n_elem = (long long)in_sizes[0];  // B * 64
    int nvec = (int)(n_elem >> 2);
    float inv_n = 1.0f / (float)n_elem;

    if (nvec == NITER * STRIDE) {
        coral_fast_kernel<<<NBLOCKS, NTHREADS>>>(logits4, targets32, inv_n, out);
    } else {
        coral_generic_kernel<<<NBLOCKS, NTHREADS>>>(logits4, targets32, nvec,
                                                    inv_n, out);
    }
}

// round 7
// speedup vs baseline: 1.1450x; 1.1450x over previous
#include <cuda_runtime.h>
#include <cuda_bf16.h>

// CoralLossV2: mean over (B, Km1=64) of BCE-with-logits(logits, levels),
// levels[i,k] = (targets[i] > k).
//
// Identity: max(x,0) - x*z + log1p(exp(-|x|)) = softplus((1-2z)*x)
//         = ln2 * log2(1 + 2^(y*log2e)),  y = z ? -x : x
//
// R6: softplus math (R5) at R4's launch shape: 2048 blocks x 256, NITER=16,
// __launch_bounds__(256,8) pins regs<=32 so 8 blocks/SM (full 2048 thr/SM).

#define NBLOCKS  2048
#define NTHREADS 256
#define NITER    16                      // vec4 per thread on the fast path
#define STRIDE   (NBLOCKS * NTHREADS)    // 524288, multiple of 16
#define TSTEP    ((STRIDE >> 4) * 2)     // int32 stride into int64 targets

#define LOG2E 1.4426950408889634f
#define LN2   0.6931471805599453f

__device__ float g_partials[NBLOCKS];
__device__ unsigned int g_counter = 0;   // self-resetting each launch

__device__ __forceinline__ float ex2f(float x) {
    float r; asm("ex2.approx.ftz.f32 %0, %1;" : "=f"(r) : "f"(x)); return r;
}
__device__ __forceinline__ float lg2f(float x) {
    float r; asm("lg2.approx.ftz.f32 %0, %1;" : "=f"(r) : "f"(x)); return r;
}

// softplus((1-2z)x) in log2 units: log2(1 + 2^(y*log2e))
__device__ __forceinline__ void proc1(float x, bool z, float& acc2) {
    float y = z ? -x : x;
    float e = ex2f(y * LOG2E);
    acc2 += lg2f(1.0f + e);
}

__device__ __forceinline__ void proc4(float4 v, int c /* t - kbase */,
                                      float& acc2) {
    proc1(v.x, c > 0, acc2);
    proc1(v.y, c > 1, acc2);
    proc1(v.z, c > 2, acc2);
    proc1(v.w, c > 3, acc2);
}

__device__ __forceinline__ float block_reduce(float acc, float* warp_sums) {
    #pragma unroll
    for (int off = 16; off > 0; off >>= 1)
        acc += __shfl_xor_sync(0xFFFFFFFF, acc, off);
    int lane = threadIdx.x & 31;
    int wid  = threadIdx.x >> 5;
    if (lane == 0) warp_sums[wid] = acc;
    __syncthreads();
    float s = 0.0f;
    if (wid == 0) {
        s = (lane < NTHREADS / 32) ? warp_sums[lane] : 0.0f;
        #pragma unroll
        for (int off = 4; off > 0; off >>= 1)
            s += __shfl_xor_sync(0xFFFFFFFF, s, off);
    }
    return s;  // valid in warp 0 lane 0
}

__device__ __forceinline__ void finish(float bsum, float inv_n,
                                       float* __restrict__ out,
                                       float* warp_sums) {
    __shared__ bool is_last;
    if (threadIdx.x == 0) {
        g_partials[blockIdx.x] = bsum;
        __threadfence();
        unsigned int done = atomicAdd(&g_counter, 1u);
        is_last = (done == (unsigned int)(gridDim.x - 1));
    }
    __syncthreads();
    if (is_last) {
        float facc = 0.0f;
        for (int j = threadIdx.x; j < (int)gridDim.x; j += NTHREADS)
            facc += g_partials[j];
        __syncthreads();
        float fsum = block_reduce(facc, warp_sums);
        if (threadIdx.x == 0) {
            out[0] = fsum * inv_n;
            g_counter = 0;
        }
    }
}

__global__ __launch_bounds__(NTHREADS, 8)   // pin regs<=32 -> 8 blocks/SM
void coral_fast_kernel(const float4* __restrict__ logits4,
                       const int* __restrict__ targets32,
                       float inv_n, float* __restrict__ out) {
    const int tid = blockIdx.x * NTHREADS + threadIdx.x;
    const int kb  = (tid & 15) << 2;            // loop-invariant
    const float4* p  = logits4 + tid;
    const int*    tp = targets32 + ((tid >> 4) << 1);

    float acc2 = 0.0f;

    #pragma unroll
    for (int mm = 0; mm < NITER / 4; mm++) {
        float4 v0 = __ldcs(p + (size_t)(mm * 4 + 0) * STRIDE);
        float4 v1 = __ldcs(p + (size_t)(mm * 4 + 1) * STRIDE);
        float4 v2 = __ldcs(p + (size_t)(mm * 4 + 2) * STRIDE);
        float4 v3 = __ldcs(p + (size_t)(mm * 4 + 3) * STRIDE);
        int t0 = __ldg(tp + (mm * 4 + 0) * TSTEP);
        int t1 = __ldg(tp + (mm * 4 + 1) * TSTEP);
        int t2 = __ldg(tp + (mm * 4 + 2) * TSTEP);
        int t3 = __ldg(tp + (mm * 4 + 3) * TSTEP);
        proc4(v0, t0 - kb, acc2);
        proc4(v1, t1 - kb, acc2);
        proc4(v2, t2 - kb, acc2);
        proc4(v3, t3 - kb, acc2);
    }

    float acc = LN2 * acc2;

    __shared__ float warp_sums[NTHREADS / 32];
    float bsum = block_reduce(acc, warp_sums);
    finish(bsum, inv_n, out, warp_sums);
}

// Generic fallback (Km1 = 64 layout, arbitrary nvec)
__global__ __launch_bounds__(NTHREADS)
void coral_generic_kernel(const float4* __restrict__ logits4,
                          const int* __restrict__ targets32,
                          int nvec, float inv_n, float* __restrict__ out) {
    const int tid    = blockIdx.x * blockDim.x + threadIdx.x;
    const int stride = gridDim.x * blockDim.x;

    float acc2 = 0.0f;
    for (int i = tid; i < nvec; i += stride) {
        float4 v = logits4[i];
        int t = targets32[(i >> 4) * 2];
        proc4(v, t - ((i & 15) << 2), acc2);
    }
    float acc = LN2 * acc2;

    __shared__ float warp_sums[NTHREADS / 32];
    float bsum = block_reduce(acc, warp_sums);
    finish(bsum, inv_n, out, warp_sums);
}

extern "C" void kernel_launch(void* const* d_in, const int* in_sizes, int n_in,
                              void* d_out, int out_size) {
    const float4* logits4   = (const float4*)d_in[0];
    const int*    targets32 = (const int*)d_in[1];  // int64 low words (targets >= 0)
    float*        out       = (float*)d_out;

    long long n_elem = (long long)in_sizes[0];  // B * 64
    int nvec = (int)(n_elem >> 2);
    float inv_n = 1.0f / (float)n_elem;

    if (nvec == NITER * STRIDE) {
        coral_fast_kernel<<<NBLOCKS, NTHREADS>>>(logits4, targets32, inv_n, out);
    } else {
        coral_generic_kernel<<<NBLOCKS, NTHREADS>>>(logits4, targets32, nvec,
                                                    inv_n, out);
    }
}